// round 7
// baseline (speedup 1.0000x reference)
#include <cuda_runtime.h>
#include <cstdint>
#include <math.h>

#define BB 256
#define TT 256
#define EE 384
#define HH 6
#define DD 64
#define NHD (HH*DD)           // 384
#define MROWS (BB*TT)         // 65536

// Scratch (device globals — allocation-free rule)
__device__ float g_Q[(size_t)BB*HH*TT*DD];     // [b][h][t][d]
__device__ float g_K[(size_t)BB*HH*TT*DD];
__device__ float g_V[(size_t)BB*HH*TT*DD];
__device__ float g_att[(size_t)BB*TT*NHD];     // [b][s][h*64+d]

// ---------------------------------------------------------------------------
// mma.sync m16n8k8 tf32 (legacy tensor-core path; compute_103-safe PTX)
// A row-major frag: a0:(g,t) a1:(g+8,t) a2:(g,t+4) a3:(g+8,t+4)
// B col-major frag: b0:(t,g)  b1:(t+4,g)        [g=lane>>2, t=lane&3]
// C: c0:(g,2t) c1:(g,2t+1) c2:(g+8,2t) c3:(g+8,2t+1)
// ---------------------------------------------------------------------------
__device__ __forceinline__ void mma_tf32(float* c, const uint32_t* a, const uint32_t* b) {
    asm volatile(
        "mma.sync.aligned.m16n8k8.row.col.f32.tf32.tf32.f32 "
        "{%0,%1,%2,%3}, {%4,%5,%6,%7}, {%8,%9}, {%0,%1,%2,%3};\n"
        : "+f"(c[0]), "+f"(c[1]), "+f"(c[2]), "+f"(c[3])
        : "r"(a[0]), "r"(a[1]), "r"(a[2]), "r"(a[3]), "r"(b[0]), "r"(b[1]));
}

// Round-to-nearest fp32 -> tf32 (removes the truncation bias of the HW path)
__device__ __forceinline__ float to_tf32(float x) {
    uint32_t r;
    asm("cvt.rna.tf32.f32 %0, %1;" : "=r"(r) : "f"(x));
    return __uint_as_float(r);
}

#define AS_STRIDE 36    // floats; conflict-free for frag loads
#define BS_STRIDE 136

// ---------------------------------------------------------------------------
// Kernel 1: QKV projection via tensor cores.
// Grid (512, 9): by/3 -> which of {Q,K,V}; by%3 -> 128-col tile of (h,d).
// CTA tile 128x128, K=384 in 12 chunks of 32. 8 warps: warp tile 32x64.
// ---------------------------------------------------------------------------
__global__ __launch_bounds__(256, 2) void qkv_mma_kernel(
    const float* __restrict__ x,
    const float* __restrict__ Wq,
    const float* __restrict__ Wk,
    const float* __restrict__ Wv)
{
    __shared__ float As[128 * AS_STRIDE];   // [m][k]
    __shared__ float Bs[32 * BS_STRIDE];    // [k][n]

    const int tid = threadIdx.x;
    const int wid = tid >> 5;
    const int lane = tid & 31;
    const int g = lane >> 2;
    const int tg = lane & 3;

    const int mBase = blockIdx.x * 128;
    const int by    = blockIdx.y;
    const int which = by / 3;
    const int r0    = (by % 3) * 128;

    const float* __restrict__ W = (which == 0) ? Wq : (which == 1) ? Wk : Wv;
    float* __restrict__ dst = (which == 0) ? g_Q : (which == 1) ? g_K : g_V;

    const int warp_m = (wid & 3) * 32;
    const int warp_n = (wid >> 2) * 64;

    const int a_r  = tid >> 1;            // A row 0..127
    const int a_q  = (tid & 1) * 16;      // A col half
    const int nn   = tid & 127;           // B col within tile
    const int kpar = tid >> 7;            // 0/1 -> even/odd k
    const int hd   = r0 + nn;
    const float* __restrict__ wcol = W + (size_t)(hd >> 6) * EE * DD + (hd & 63);

    float c[2][8][4];
#pragma unroll
    for (int i = 0; i < 2; i++)
#pragma unroll
        for (int j = 0; j < 8; j++)
#pragma unroll
            for (int q = 0; q < 4; q++) c[i][j][q] = 0.f;

    for (int e0 = 0; e0 < EE; e0 += 32) {
        // A tile: 128x32, row-major, stride 36, RN-converted to tf32
        {
            const float* ap = x + (size_t)(mBase + a_r) * EE + e0 + a_q;
            float* as = &As[a_r * AS_STRIDE + a_q];
#pragma unroll
            for (int i = 0; i < 4; i++) {
                float4 v = *reinterpret_cast<const float4*>(ap + 4 * i);
                as[4 * i + 0] = to_tf32(v.x);
                as[4 * i + 1] = to_tf32(v.y);
                as[4 * i + 2] = to_tf32(v.z);
                as[4 * i + 3] = to_tf32(v.w);
            }
        }
        // B tile: 32x128, [k][n], stride 136, RN-converted to tf32
#pragma unroll
        for (int i = 0; i < 16; i++) {
            const int k = kpar + 2 * i;
            Bs[k * BS_STRIDE + nn] = to_tf32(wcol[(size_t)(e0 + k) * DD]);
        }
        __syncthreads();

#pragma unroll
        for (int ks = 0; ks < 4; ks++) {
            const int k0 = ks * 8;
            uint32_t a[2][4], b[8][2];
#pragma unroll
            for (int mt = 0; mt < 2; mt++) {
                const float* ap = &As[(warp_m + mt * 16 + g) * AS_STRIDE + k0 + tg];
                a[mt][0] = __float_as_uint(ap[0]);
                a[mt][1] = __float_as_uint(ap[8 * AS_STRIDE]);
                a[mt][2] = __float_as_uint(ap[4]);
                a[mt][3] = __float_as_uint(ap[8 * AS_STRIDE + 4]);
            }
#pragma unroll
            for (int nt = 0; nt < 8; nt++) {
                const float* bp = &Bs[(k0 + tg) * BS_STRIDE + warp_n + nt * 8 + g];
                b[nt][0] = __float_as_uint(bp[0]);
                b[nt][1] = __float_as_uint(bp[4 * BS_STRIDE]);
            }
#pragma unroll
            for (int mt = 0; mt < 2; mt++)
#pragma unroll
                for (int nt = 0; nt < 8; nt++)
                    mma_tf32(c[mt][nt], a[mt], b[nt]);
        }
        __syncthreads();
    }

    // epilogue: scatter into [b][h][t][d]
#pragma unroll
    for (int mt = 0; mt < 2; mt++) {
        const int row = warp_m + mt * 16 + g;
        const int m0 = mBase + row;
        const int b0i = m0 >> 8, s0 = m0 & 255;
        const int m1 = m0 + 8;
        const int b1i = m1 >> 8, s1 = m1 & 255;
#pragma unroll
        for (int nt = 0; nt < 8; nt++) {
            const int col = warp_n + nt * 8 + 2 * tg;
            const int hd2 = r0 + col;
            const int h2 = hd2 >> 6, d2 = hd2 & 63;
            *reinterpret_cast<float2*>(
                &dst[(((size_t)b0i * HH + h2) * TT + s0) * DD + d2]) =
                make_float2(c[mt][nt][0], c[mt][nt][1]);
            *reinterpret_cast<float2*>(
                &dst[(((size_t)b1i * HH + h2) * TT + s1) * DD + d2]) =
                make_float2(c[mt][nt][2], c[mt][nt][3]);
        }
    }
}

// ---------------------------------------------------------------------------
// Kernel 2: causal attention (fp32 FFMA path — next round's target)
// ---------------------------------------------------------------------------
#define SMEM_ATTN ((64*256 + 256*64 + 8*256 + 8*64) * 4)

__global__ __launch_bounds__(256) void attn_kernel()
{
    extern __shared__ float sm[];
    float* Kt   = sm;
    float* Vs   = sm + 64 * 256;
    float* sbuf = Vs + 256 * 64;
    float* qbuf = sbuf + 8 * 256;

    const int bh = blockIdx.x;
    const int b  = bh / HH;
    const int h  = bh % HH;
    const int tid = threadIdx.x;
    const int w  = tid >> 5;
    const int L  = tid & 31;
    const size_t base = (size_t)bh * TT * DD;

    for (int idx = tid; idx < TT * (DD / 4); idx += 256) {
        int t = idx >> 4;
        int cidx = (idx & 15) * 4;
        float4 kv = *reinterpret_cast<const float4*>(&g_K[base + (size_t)t * DD + cidx]);
        Kt[(cidx + 0) * TT + t] = kv.x;
        Kt[(cidx + 1) * TT + t] = kv.y;
        Kt[(cidx + 2) * TT + t] = kv.z;
        Kt[(cidx + 3) * TT + t] = kv.w;
        float4 vv = *reinterpret_cast<const float4*>(&g_V[base + (size_t)t * DD + cidx]);
        *reinterpret_cast<float4*>(&Vs[t * DD + cidx]) = vv;
    }
    __syncthreads();

    const float scale = 0.125f;
    float* srow = sbuf + w * TT;
    float* qrow = qbuf + w * DD;

    for (int s = w; s < TT; s += 8) {
        qrow[L]      = g_Q[base + (size_t)s * DD + L];
        qrow[L + 32] = g_Q[base + (size_t)s * DD + L + 32];
        __syncwarp();
        float q[64];
#pragma unroll
        for (int dd = 0; dd < 64; dd++) q[dd] = qrow[dd];

        const int nch  = (s >> 7) + 1;
        const int npad = nch * 128;

        for (int cch = 0; cch < nch; cch++) {
            int tbase = cch * 128 + L * 4;
            float a0 = 0.f, a1 = 0.f, a2 = 0.f, a3 = 0.f;
#pragma unroll
            for (int dd = 0; dd < 64; dd++) {
                float4 kk = *reinterpret_cast<const float4*>(&Kt[dd * TT + tbase]);
                float qd = q[dd];
                a0 += qd * kk.x; a1 += qd * kk.y; a2 += qd * kk.z; a3 += qd * kk.w;
            }
            float4 sc;
            sc.x = (tbase + 0 <= s) ? a0 * scale : -3.0e38f;
            sc.y = (tbase + 1 <= s) ? a1 * scale : -3.0e38f;
            sc.z = (tbase + 2 <= s) ? a2 * scale : -3.0e38f;
            sc.w = (tbase + 3 <= s) ? a3 * scale : -3.0e38f;
            *reinterpret_cast<float4*>(&srow[tbase]) = sc;
        }
        __syncwarp();

        float mx = -3.0e38f;
        for (int t = L; t < npad; t += 32) mx = fmaxf(mx, srow[t]);
#pragma unroll
        for (int o = 16; o; o >>= 1) mx = fmaxf(mx, __shfl_xor_sync(0xffffffffu, mx, o));

        float ssum = 0.f;
        for (int t = L; t < npad; t += 32) {
            float p = __expf(srow[t] - mx);
            srow[t] = p;
            ssum += p;
        }
#pragma unroll
        for (int o = 16; o; o >>= 1) ssum += __shfl_xor_sync(0xffffffffu, ssum, o);
        float inv = 1.0f / ssum;
        __syncwarp();

        float o0 = 0.f, o1 = 0.f;
        for (int t4 = 0; t4 < npad; t4 += 4) {
            float4 p4 = *reinterpret_cast<const float4*>(&srow[t4]);
            float2 v0 = *reinterpret_cast<const float2*>(&Vs[(t4 + 0) * DD + 2 * L]);
            float2 v1 = *reinterpret_cast<const float2*>(&Vs[(t4 + 1) * DD + 2 * L]);
            float2 v2 = *reinterpret_cast<const float2*>(&Vs[(t4 + 2) * DD + 2 * L]);
            float2 v3 = *reinterpret_cast<const float2*>(&Vs[(t4 + 3) * DD + 2 * L]);
            o0 += p4.x * v0.x + p4.y * v1.x + p4.z * v2.x + p4.w * v3.x;
            o1 += p4.x * v0.y + p4.y * v1.y + p4.z * v2.y + p4.w * v3.y;
        }
        *reinterpret_cast<float2*>(
            &g_att[((size_t)b * TT + s) * NHD + h * DD + 2 * L]) =
            make_float2(o0 * inv, o1 * inv);
        __syncwarp();
    }
}

// ---------------------------------------------------------------------------
// Kernel 3: output projection via tensor cores. out = g_att @ Wo + bo
// Grid (512, 3). Same tiling as kernel 1; B[k][n] = Wo[e][n] direct.
// ---------------------------------------------------------------------------
__global__ __launch_bounds__(256, 2) void out_mma_kernel(
    const float* __restrict__ Wo,
    const float* __restrict__ bo,
    float* __restrict__ out)
{
    __shared__ float As[128 * AS_STRIDE];
    __shared__ float Bs[32 * BS_STRIDE];

    const int tid = threadIdx.x;
    const int wid = tid >> 5;
    const int lane = tid & 31;
    const int g = lane >> 2;
    const int tg = lane & 3;

    const int mBase = blockIdx.x * 128;
    const int nBase = blockIdx.y * 128;

    const int warp_m = (wid & 3) * 32;
    const int warp_n = (wid >> 2) * 64;

    const int a_r  = tid >> 1;
    const int a_q  = (tid & 1) * 16;
    const int nn   = tid & 127;
    const int kpar = tid >> 7;

    float c[2][8][4];
#pragma unroll
    for (int i = 0; i < 2; i++)
#pragma unroll
        for (int j = 0; j < 8; j++)
#pragma unroll
            for (int q = 0; q < 4; q++) c[i][j][q] = 0.f;

    for (int e0 = 0; e0 < EE; e0 += 32) {
        {
            const float* ap = g_att + (size_t)(mBase + a_r) * EE + e0 + a_q;
            float* as = &As[a_r * AS_STRIDE + a_q];
#pragma unroll
            for (int i = 0; i < 4; i++) {
                float4 v = *reinterpret_cast<const float4*>(ap + 4 * i);
                as[4 * i + 0] = to_tf32(v.x);
                as[4 * i + 1] = to_tf32(v.y);
                as[4 * i + 2] = to_tf32(v.z);
                as[4 * i + 3] = to_tf32(v.w);
            }
        }
#pragma unroll
        for (int i = 0; i < 16; i++) {
            const int k = kpar + 2 * i;
            Bs[k * BS_STRIDE + nn] = to_tf32(Wo[(size_t)(e0 + k) * EE + nBase + nn]);
        }
        __syncthreads();

#pragma unroll
        for (int ks = 0; ks < 4; ks++) {
            const int k0 = ks * 8;
            uint32_t a[2][4], b[8][2];
#pragma unroll
            for (int mt = 0; mt < 2; mt++) {
                const float* ap = &As[(warp_m + mt * 16 + g) * AS_STRIDE + k0 + tg];
                a[mt][0] = __float_as_uint(ap[0]);
                a[mt][1] = __float_as_uint(ap[8 * AS_STRIDE]);
                a[mt][2] = __float_as_uint(ap[4]);
                a[mt][3] = __float_as_uint(ap[8 * AS_STRIDE + 4]);
            }
#pragma unroll
            for (int nt = 0; nt < 8; nt++) {
                const float* bp = &Bs[(k0 + tg) * BS_STRIDE + warp_n + nt * 8 + g];
                b[nt][0] = __float_as_uint(bp[0]);
                b[nt][1] = __float_as_uint(bp[4 * BS_STRIDE]);
            }
#pragma unroll
            for (int mt = 0; mt < 2; mt++)
#pragma unroll
                for (int nt = 0; nt < 8; nt++)
                    mma_tf32(c[mt][nt], a[mt], b[nt]);
        }
        __syncthreads();
    }

#pragma unroll
    for (int mt = 0; mt < 2; mt++) {
        const int row = warp_m + mt * 16 + g;
        const int m0 = mBase + row;
        const int m1 = m0 + 8;
#pragma unroll
        for (int nt = 0; nt < 8; nt++) {
            const int col = warp_n + nt * 8 + 2 * tg;
            const float2 bias = *reinterpret_cast<const float2*>(&bo[nBase + col]);
            *reinterpret_cast<float2*>(&out[(size_t)m0 * EE + nBase + col]) =
                make_float2(c[mt][nt][0] + bias.x, c[mt][nt][1] + bias.y);
            *reinterpret_cast<float2*>(&out[(size_t)m1 * EE + nBase + col]) =
                make_float2(c[mt][nt][2] + bias.x, c[mt][nt][3] + bias.y);
        }
    }
}

// ---------------------------------------------------------------------------
extern "C" void kernel_launch(void* const* d_in, const int* in_sizes, int n_in,
                              void* d_out, int out_size)
{
    const float* x  = (const float*)d_in[0];
    const float* Wq = (const float*)d_in[1];
    const float* Wk = (const float*)d_in[2];
    const float* Wv = (const float*)d_in[3];
    const float* Wo = (const float*)d_in[4];
    const float* bo = (const float*)d_in[5];
    float* out = (float*)d_out;

    cudaFuncSetAttribute(attn_kernel,
                         cudaFuncAttributeMaxDynamicSharedMemorySize, SMEM_ATTN);

    dim3 g1(MROWS / 128, 9);
    qkv_mma_kernel<<<g1, 256>>>(x, Wq, Wk, Wv);

    attn_kernel<<<BB * HH, 256, SMEM_ATTN>>>();

    dim3 g3(MROWS / 128, 3);
    out_mma_kernel<<<g3, 256>>>(Wo, bo, out);
}